// round 12
// baseline (speedup 1.0000x reference)
#include <cuda_runtime.h>
#include <cuda_bf16.h>

// Problem constants (fixed by the reference)
#define BB 2
#define CC 64
#define HH 512
#define WW 512
#define HW (HH * WW)          // 262144
#define NN 4096
#define KK 5
#define NPAIR (BB * NN)       // 8192
#define INV_MAXDIST (1.0f / 724.07733f)
#define FEAT_THRESH_NOMATCH 16.0f
// fixed-point: fp_i = total_i * FP_SCALE, FP_SCALE = (1/24576) * 2^48 = 2^35/3
// finalize: out = (sum fp_i) * 2^-48
#define FP_SCALE (34359738368.0f / 3.0f)          // 1.1453246123e10
#define FP_INV   (1.0 / 281474976710656.0)        // 2^-48
#define QPTS 1024             // points per sorter block (quarter of a set)
#define MATCH_BLOCKS 64

// Scratch (allocation-free rule: __device__ globals)
__device__ float g_fr[NPAIR * CC];      // compacted ref features   [b][i][c]
__device__ float g_fo[NPAIR * CC];      // compacted other features [b][i][c]
__device__ int   g_order[4][NN];        // per set: packed (lin<<12 | point id)
__device__ unsigned long long g_isum;   // fixed-point loss accumulator
__device__ unsigned int       g_ticket; // completion counter (blocks)

// ---------------------------------------------------------------------------
// Kernel S: 16-way parallel counting sort. Block = (set, quarter): sorts its
// 1024 points by y into g_order[set][quarter*1024 .. +1024). Quarters are
// independent permutations; gather chunks (32 points) never cross the 1024-
// aligned quarter boundary, and downstream results are id-indexed, so the
// within-bucket permutation nondeterminism never reaches the output.
// ---------------------------------------------------------------------------
__global__ void __launch_bounds__(512) sort_kernel(
        const int* __restrict__ inds_ref,
        const int* __restrict__ inds_other) {
    if (blockIdx.x == 0 && threadIdx.x == 0) {
        g_isum = 0ULL;
        g_ticket = 0u;
    }
    int s = blockIdx.x >> 2;          // set: 0,1 = ref b0,b1 ; 2,3 = oth b0,b1
    int q = blockIdx.x & 3;           // quarter
    int t = s >> 1, b = s & 1;
    const int* inds = t ? inds_other : inds_ref;
    int i0 = q * QPTS;                // first point index of this quarter

    __shared__ int lin_s[QPTS];       // 4 KB
    __shared__ int hist[512];
    __shared__ int wsum[16];
    __shared__ int offs[512];

    int tid  = threadIdx.x;
    int lane = tid & 31;
    int w    = tid >> 5;

    hist[tid] = 0;
    __syncthreads();

    // 2 points per thread
#pragma unroll
    for (int r = 0; r < 2; r++) {
        int i = i0 + tid + r * 512;
        int x = inds[b * 2 * NN + i];
        int y = inds[b * 2 * NN + NN + i];
        int lin = (y << 9) | x;       // 512*y + x
        lin_s[tid + r * 512] = lin;
        atomicAdd(&hist[y], 1);
    }
    __syncthreads();

    // two-level scan of 512 buckets with 512 threads
    int v = hist[tid];
#pragma unroll
    for (int d = 1; d < 32; d <<= 1) {
        int u = __shfl_up_sync(0xFFFFFFFFu, v, d);
        if (lane >= d) v += u;
    }
    if (lane == 31) wsum[w] = v;
    __syncthreads();
    if (tid < 32) {
        int u = (tid < 16) ? wsum[tid] : 0;
#pragma unroll
        for (int d = 1; d < 16; d <<= 1) {
            int x2 = __shfl_up_sync(0xFFFFFFFFu, u, d);
            if (lane >= d) u += x2;
        }
        if (tid < 16) wsum[tid] = u;
    }
    __syncthreads();
    offs[tid] = ((w > 0) ? wsum[w - 1] : 0) + v - hist[tid];  // exclusive
    __syncthreads();

#pragma unroll
    for (int r = 0; r < 2; r++) {
        int li  = tid + r * 512;
        int lin = lin_s[li];
        int pos = atomicAdd(&offs[lin >> 9], 1);
        g_order[s][i0 + pos] = (lin << 12) | (i0 + li);
    }
}

// ---------------------------------------------------------------------------
// Kernel A: sorted gather. warp <-> (set, channel-group, chunk of 32 sorted
// points). Per load-slot a warp reads 32 ascending addresses within one
// quarter-sorted stream -> DRAM row-buffer hits + coalescer line merges.
// ---------------------------------------------------------------------------
__global__ void __launch_bounds__(256) gather_sorted_kernel(
        const float* __restrict__ ref,
        const float* __restrict__ oth) {
    int gw   = (blockIdx.x * blockDim.x + threadIdx.x) >> 5;  // 0..8191
    int lane = threadIdx.x & 31;
    int s    = gw >> 11;          // set (4)
    int qg   = (gw >> 7) & 15;    // channel group (16)
    int chnk = gw & 127;          // sorted chunk (128)
    int t = s >> 1, b = s & 1;

    int packed = g_order[s][chnk * 32 + lane];
    int lin = packed >> 12;
    int id  = packed & 4095;

    const float* src = (t ? oth : ref) + (size_t)(b * CC + 4 * qg) * HW + lin;
    float v0 = __ldg(src + 0 * HW);
    float v1 = __ldg(src + 1 * HW);
    float v2 = __ldg(src + 2 * HW);
    float v3 = __ldg(src + 3 * HW);

    float* dst = (t ? g_fo : g_fr) + (size_t)((b << 12) | id) * CC + 4 * qg;
    *reinterpret_cast<float4*>(dst) = make_float4(v0, v1, v2, v3);
}

// ---------------------------------------------------------------------------
// Kernel B: 64 blocks; each warp loops over 16 match pairs (features L2-
// resident). Per-block smem reduction -> ONE global atomic + ticket per block
// (64 total). Integer adds -> bit-deterministic across graph replays.
// ---------------------------------------------------------------------------
__global__ void __launch_bounds__(256) match_kernel(
        const float* __restrict__ weights,
        const int* __restrict__ inds_ref,
        const int* __restrict__ rand_inds,
        float* __restrict__ out) {
    __shared__ long long s_fp[8];
    int lane = threadIdx.x & 31;
    int wib  = threadIdx.x >> 5;
    int gw0  = blockIdx.x * 8 + wib;       // first pair slot of this warp

    long long fp_acc = 0;
    for (int pair = gw0; pair < NPAIR; pair += MATCH_BLOCKS * 8) {
        int b = pair >> 12;
        int i = pair & (NN - 1);

        const float2* frp = reinterpret_cast<const float2*>(g_fr + (size_t)pair * CC);
        const float2* fop = reinterpret_cast<const float2*>(g_fo + (size_t)pair * CC);
        float2 fr = frp[lane];
        float2 fo = fop[lane];
        float d0 = fr.x - fo.x, d1 = fr.y - fo.y;
        float sm = d0 * d0 + d1 * d1;

        int   jarr[KK];
        float sk[KK];
        const int* ri = rand_inds + (size_t)pair * KK;
#pragma unroll
        for (int k = 0; k < KK; k++) {
            int j = __ldg(ri + k);             // uniform across warp
            jarr[k] = j;
            const float2* fo_j =
                reinterpret_cast<const float2*>(g_fo + (size_t)(b * NN + j) * CC);
            float2 fj = fo_j[lane];
            float e0 = fr.x - fj.x, e1 = fr.y - fj.y;
            sk[k] = e0 * e0 + e1 * e1;
        }

#pragma unroll
        for (int off = 16; off > 0; off >>= 1) {
            sm += __shfl_down_sync(0xFFFFFFFFu, sm, off);
#pragma unroll
            for (int k = 0; k < KK; k++)
                sk[k] += __shfl_down_sync(0xFFFFFFFFu, sk[k], off);
        }

        if (lane == 0) {
            int xr = inds_ref[b * 2 * NN + i];
            int yr = inds_ref[b * 2 * NN + NN + i];
            float total = weights[b * NN + i] * fmaxf(sm, 0.0f);
#pragma unroll
            for (int k = 0; k < KK; k++) {
                int j  = jarr[k];
                float xj = (float)inds_ref[b * 2 * NN + j];
                float yj = (float)inds_ref[b * 2 * NN + NN + j];
                float dx = (float)xr - xj;
                float dy = (float)yr - yj;
                float dist = sqrtf(dx * dx + dy * dy);
                total += (-dist * INV_MAXDIST) * fminf(sk[k], FEAT_THRESH_NOMATCH);
            }
            fp_acc += llrintf(total * FP_SCALE);
        }
    }

    if (lane == 0) s_fp[wib] = fp_acc;
    __syncthreads();
    if (threadIdx.x == 0) {
        long long bsum = 0;
#pragma unroll
        for (int k = 0; k < 8; k++) bsum += s_fp[k];
        atomicAdd(&g_isum, (unsigned long long)bsum);
        __threadfence();
        unsigned int t = atomicAdd(&g_ticket, 1u);
        if (t == MATCH_BLOCKS - 1) {
            long long s = (long long)g_isum;
            out[0] = (float)((double)s * FP_INV);
        }
    }
}

extern "C" void kernel_launch(void* const* d_in, const int* in_sizes, int n_in,
                              void* d_out, int out_size) {
    const float* inputs_ref   = (const float*)d_in[0];
    const float* inputs_other = (const float*)d_in[1];
    const float* weights      = (const float*)d_in[2];
    const int*   inds_ref     = (const int*)d_in[3];
    const int*   inds_other   = (const int*)d_in[4];
    const int*   rand_inds    = (const int*)d_in[5];
    float* out = (float*)d_out;

    sort_kernel<<<16, 512>>>(inds_ref, inds_other);
    gather_sorted_kernel<<<1024, 256>>>(inputs_ref, inputs_other);
    match_kernel<<<MATCH_BLOCKS, 256>>>(weights, inds_ref, rand_inds, out);
}

// round 13
// speedup vs baseline: 2.4099x; 2.4099x over previous
#include <cuda_runtime.h>
#include <cuda_bf16.h>

// Problem constants (fixed by the reference)
#define BB 2
#define CC 64
#define HH 512
#define WW 512
#define HW (HH * WW)          // 262144
#define NN 4096
#define KK 5
#define NPAIR (BB * NN)       // 8192
#define INV_MAXDIST (1.0f / 724.07733f)
#define FEAT_THRESH_NOMATCH 16.0f
// fixed-point: fp_i = total_i * FP_SCALE, FP_SCALE = (1/24576) * 2^48 = 2^35/3
// finalize: out = (sum fp_i) * 2^-48
#define FP_SCALE (34359738368.0f / 3.0f)          // 1.1453246123e10
#define FP_INV   (1.0 / 281474976710656.0)        // 2^-48
#define QPTS 1024             // points per quarter
#define MATCH_BLOCKS 1024

// Scratch (allocation-free rule: __device__ globals)
__device__ float g_fr[NPAIR * CC];      // compacted ref features   [b][i][c]
__device__ float g_fo[NPAIR * CC];      // compacted other features [b][i][c]
__device__ unsigned long long g_isum;   // fixed-point loss accumulator
__device__ unsigned int       g_ticket; // completion counter (blocks)

// ---------------------------------------------------------------------------
// Kernel 1: fused block-local sort + gather. 128 blocks x 256 threads, one
// wave. Block (s, q, cc): set s (0,1=ref b0/b1; 2,3=oth b0/b1), quarter q,
// channel-chunk cc (2 channel-groups of 4). Each block counting-sorts its
// quarter's 1024 points by y in SMEM (redundant across the 8 cc-blocks of a
// quarter -- no inter-block dependency), then gathers with warp<->32 sorted
// points in one plane (DRAM row locality). Results are id-indexed, so the
// within-bucket permutation nondeterminism never reaches the output.
// ---------------------------------------------------------------------------
__global__ void __launch_bounds__(256) sortgather_kernel(
        const float* __restrict__ ref,
        const float* __restrict__ oth,
        const int* __restrict__ inds_ref,
        const int* __restrict__ inds_other) {
    __shared__ int lin_s[QPTS];       // 4 KB
    __shared__ int order_s[QPTS];     // 4 KB  packed (lin<<12 | global id)
    __shared__ int hist[512];
    __shared__ int offs[512];
    __shared__ int wsum[8];

    int tid  = threadIdx.x;
    int lane = tid & 31;
    int wib  = tid >> 5;              // warp in block (0..7)
    int bx   = blockIdx.x;
    int cc   = bx & 7;                // channel chunk (8): channels 8cc..8cc+7
    int q    = (bx >> 3) & 3;         // quarter
    int s    = bx >> 5;               // set
    int t = s >> 1, b = s & 1;

    if (bx == 0 && tid == 0) {        // reset accumulators for graph replay
        g_isum = 0ULL;
        g_ticket = 0u;
    }

    const int* inds = t ? inds_other : inds_ref;
    int i0 = q * QPTS;

    // ---- Phase 1: block-local counting sort of 1024 points by y ----
    hist[tid] = 0;
    hist[tid + 256] = 0;
    __syncthreads();

#pragma unroll
    for (int r = 0; r < 4; r++) {
        int il = tid + r * 256;           // local 0..1023
        int i  = i0 + il;
        int x  = inds[b * 2 * NN + i];
        int y  = inds[b * 2 * NN + NN + i];
        int lin = (y << 9) | x;           // 512*y + x
        lin_s[il] = lin;
        atomicAdd(&hist[y], 1);
    }
    __syncthreads();

    // scan 512 buckets with 256 threads (thread owns buckets 2t, 2t+1)
    int h0 = hist[2 * tid];
    int h1 = hist[2 * tid + 1];
    int psum = h0 + h1;
    int v = psum;
#pragma unroll
    for (int d = 1; d < 32; d <<= 1) {
        int u = __shfl_up_sync(0xFFFFFFFFu, v, d);
        if (lane >= d) v += u;
    }
    if (lane == 31) wsum[wib] = v;
    __syncthreads();
    if (tid < 32) {
        int u = (tid < 8) ? wsum[tid] : 0;
#pragma unroll
        for (int d = 1; d < 8; d <<= 1) {
            int x2 = __shfl_up_sync(0xFFFFFFFFu, u, d);
            if (lane >= d) u += x2;
        }
        if (tid < 8) wsum[tid] = u;
    }
    __syncthreads();
    int base = ((wib > 0) ? wsum[wib - 1] : 0) + (v - psum);
    offs[2 * tid]     = base;
    offs[2 * tid + 1] = base + h0;
    __syncthreads();

#pragma unroll
    for (int r = 0; r < 4; r++) {
        int il  = tid + r * 256;
        int lin = lin_s[il];
        int pos = atomicAdd(&offs[lin >> 9], 1);
        order_s[pos] = (lin << 12) | (i0 + il);
    }
    __syncthreads();

    // ---- Phase 2: gather. 64 slots = 2 channel-groups x 32 chunks ----
    const float* srcbase = t ? oth : ref;
    float* dstbase = t ? g_fo : g_fr;
#pragma unroll
    for (int slot = wib; slot < 64; slot += 8) {
        int cg    = 2 * cc + (slot >> 5);   // channel group 0..15
        int chunk = slot & 31;

        int packed = order_s[chunk * 32 + lane];
        int lin = packed >> 12;
        int id  = packed & 4095;

        const float* src = srcbase + (size_t)(b * CC + 4 * cg) * HW + lin;
        float v0 = __ldg(src + 0 * HW);
        float v1 = __ldg(src + 1 * HW);
        float v2 = __ldg(src + 2 * HW);
        float v3 = __ldg(src + 3 * HW);

        float* dst = dstbase + (size_t)((b << 12) | id) * CC + 4 * cg;
        *reinterpret_cast<float4*>(dst) = make_float4(v0, v1, v2, v3);
    }
}

// ---------------------------------------------------------------------------
// Kernel 2: match. 1024 blocks x 256; ONE pair per warp (shuffle chain paid
// once per warp). Per-block smem reduction -> one integer atomic + ticket per
// block. Integer adds are associative -> bit-deterministic across replays.
// ---------------------------------------------------------------------------
__global__ void __launch_bounds__(256) match_kernel(
        const float* __restrict__ weights,
        const int* __restrict__ inds_ref,
        const int* __restrict__ rand_inds,
        float* __restrict__ out) {
    __shared__ long long s_fp[8];
    int gwarp = (blockIdx.x * blockDim.x + threadIdx.x) >> 5;
    int lane  = threadIdx.x & 31;
    int wib   = threadIdx.x >> 5;
    int b = gwarp >> 12;
    int i = gwarp & (NN - 1);

    const float2* frp = reinterpret_cast<const float2*>(g_fr + (size_t)gwarp * CC);
    const float2* fop = reinterpret_cast<const float2*>(g_fo + (size_t)gwarp * CC);
    float2 fr = frp[lane];
    float2 fo = fop[lane];
    float d0 = fr.x - fo.x, d1 = fr.y - fo.y;
    float sm = d0 * d0 + d1 * d1;

    int   jarr[KK];
    float sk[KK];
    const int* ri = rand_inds + (size_t)gwarp * KK;
#pragma unroll
    for (int k = 0; k < KK; k++) {
        int j = __ldg(ri + k);             // uniform across warp (broadcast)
        jarr[k] = j;
        const float2* fo_j =
            reinterpret_cast<const float2*>(g_fo + (size_t)(b * NN + j) * CC);
        float2 fj = fo_j[lane];
        float e0 = fr.x - fj.x, e1 = fr.y - fj.y;
        sk[k] = e0 * e0 + e1 * e1;
    }

#pragma unroll
    for (int off = 16; off > 0; off >>= 1) {
        sm += __shfl_down_sync(0xFFFFFFFFu, sm, off);
#pragma unroll
        for (int k = 0; k < KK; k++)
            sk[k] += __shfl_down_sync(0xFFFFFFFFu, sk[k], off);
    }

    if (lane == 0) {
        int xr = inds_ref[b * 2 * NN + i];
        int yr = inds_ref[b * 2 * NN + NN + i];
        float total = weights[b * NN + i] * fmaxf(sm, 0.0f);
#pragma unroll
        for (int k = 0; k < KK; k++) {
            int j  = jarr[k];
            float xj = (float)inds_ref[b * 2 * NN + j];
            float yj = (float)inds_ref[b * 2 * NN + NN + j];
            float dx = (float)xr - xj;
            float dy = (float)yr - yj;
            float dist = sqrtf(dx * dx + dy * dy);
            total += (-dist * INV_MAXDIST) * fminf(sk[k], FEAT_THRESH_NOMATCH);
        }
        s_fp[wib] = llrintf(total * FP_SCALE);
    }
    __syncthreads();

    if (threadIdx.x == 0) {
        long long bsum = 0;
#pragma unroll
        for (int k = 0; k < 8; k++) bsum += s_fp[k];
        atomicAdd(&g_isum, (unsigned long long)bsum);
        __threadfence();
        unsigned int t = atomicAdd(&g_ticket, 1u);
        if (t == MATCH_BLOCKS - 1) {
            long long s = (long long)g_isum;
            out[0] = (float)((double)s * FP_INV);
        }
    }
}

extern "C" void kernel_launch(void* const* d_in, const int* in_sizes, int n_in,
                              void* d_out, int out_size) {
    const float* inputs_ref   = (const float*)d_in[0];
    const float* inputs_other = (const float*)d_in[1];
    const float* weights      = (const float*)d_in[2];
    const int*   inds_ref     = (const int*)d_in[3];
    const int*   inds_other   = (const int*)d_in[4];
    const int*   rand_inds    = (const int*)d_in[5];
    float* out = (float*)d_out;

    // 128 blocks: 4 sets x 4 quarters x 8 channel-chunks, one wave
    sortgather_kernel<<<128, 256>>>(inputs_ref, inputs_other,
                                    inds_ref, inds_other);
    match_kernel<<<MATCH_BLOCKS, 256>>>(weights, inds_ref, rand_inds, out);
}